// round 1
// baseline (speedup 1.0000x reference)
#include <cuda_runtime.h>

// Problem constants
#define NN 4
#define CC 64
#define HH 96
#define WW 96
#define PP (HH * WW)       // 9216 pixels per image
#define OO 1728            // 3 * C * 9 generated kernel channels
#define KTOT 2304          // 256 * 9 reduction dim of fuse conv

// Scratch (alloc-free rule: __device__ globals)
__device__ float g_kern[(size_t)NN * OO * PP];     // ~255 MB: per-pixel generated kernels
__device__ float g_cat[(size_t)NN * 4 * CC * PP];  // ~38 MB: concat(x, r1, r3, r5)
__device__ float g_wT[KTOT * CC];                  // fuse_w transposed to [k][co]

// ---- packed fp32x2 helpers (full-rate FFMA path on sm_103a) ----
static __device__ __forceinline__ unsigned long long pack2(float lo, float hi) {
    unsigned long long r;
    asm("mov.b64 %0, {%1,%2};" : "=l"(r) : "f"(lo), "f"(hi));
    return r;
}
static __device__ __forceinline__ void unpack2(unsigned long long v, float& lo, float& hi) {
    asm("mov.b64 {%0,%1}, %2;" : "=f"(lo), "=f"(hi) : "l"(v));
}
static __device__ __forceinline__ void fma2(unsigned long long& d, unsigned long long a, unsigned long long b) {
    asm("fma.rn.f32x2 %0, %1, %2, %3;" : "=l"(d) : "l"(a), "l"(b), "l"(d));
}

// ============================================================
// Stage 1: kern[n,o,p] = sum_k gen_w[o,k] * y[n,k,p] + gen_b[o]
// GEMM per n: M=1728 (o), N=9216 (p), K=64. Tile 64x128, K in one pass.
// ============================================================
__global__ void __launch_bounds__(256) stage1_gemm(
    const float* __restrict__ gen_w, const float* __restrict__ gen_b,
    const float* __restrict__ y)
{
    __shared__ __align__(16) float As[64][64];   // [k][o]  (transposed gen_w tile)
    __shared__ __align__(16) float Bs[64][128];  // [k][p]
    const int n  = blockIdx.z;
    const int o0 = blockIdx.y * 64;
    const int p0 = blockIdx.x * 128;
    const int tid = threadIdx.x;
    const int tx = tid & 15, ty = tid >> 4;

    // Load A tile (gen_w rows), store transposed into smem
#pragma unroll
    for (int t = 0; t < 4; t++) {
        int idx = tid + t * 256;     // float4 id, 0..1023
        int o  = idx >> 4;
        int c4 = (idx & 15) * 4;
        float4 v = *(const float4*)(gen_w + (size_t)(o0 + o) * 64 + c4);
        As[c4 + 0][o] = v.x;
        As[c4 + 1][o] = v.y;
        As[c4 + 2][o] = v.z;
        As[c4 + 3][o] = v.w;
    }
    // Load B tile (y), coalesced float4
    const float* yb = y + (size_t)n * CC * PP + p0;
#pragma unroll
    for (int t = 0; t < 8; t++) {
        int idx = tid + t * 256;     // float4 id, 0..2047
        int k  = idx >> 5;
        int c4 = (idx & 31) * 4;
        *(float4*)&Bs[k][c4] = *(const float4*)(yb + (size_t)k * PP + c4);
    }
    __syncthreads();

    unsigned long long acc[4][4];    // 4 o-rows x 4 fp32-pairs (8 p cols)
#pragma unroll
    for (int i = 0; i < 4; i++)
#pragma unroll
        for (int j = 0; j < 4; j++) acc[i][j] = 0ull;

#pragma unroll 8
    for (int k = 0; k < 64; k++) {
        float4 a = *(float4*)&As[k][ty * 4];
        ulonglong2 b0 = *(ulonglong2*)&Bs[k][tx * 8];
        ulonglong2 b1 = *(ulonglong2*)&Bs[k][tx * 8 + 4];
        unsigned long long ap0 = pack2(a.x, a.x);
        unsigned long long ap1 = pack2(a.y, a.y);
        unsigned long long ap2 = pack2(a.z, a.z);
        unsigned long long ap3 = pack2(a.w, a.w);
        fma2(acc[0][0], ap0, b0.x); fma2(acc[0][1], ap0, b0.y);
        fma2(acc[0][2], ap0, b1.x); fma2(acc[0][3], ap0, b1.y);
        fma2(acc[1][0], ap1, b0.x); fma2(acc[1][1], ap1, b0.y);
        fma2(acc[1][2], ap1, b1.x); fma2(acc[1][3], ap1, b1.y);
        fma2(acc[2][0], ap2, b0.x); fma2(acc[2][1], ap2, b0.y);
        fma2(acc[2][2], ap2, b1.x); fma2(acc[2][3], ap2, b1.y);
        fma2(acc[3][0], ap3, b0.x); fma2(acc[3][1], ap3, b0.y);
        fma2(acc[3][2], ap3, b1.x); fma2(acc[3][3], ap3, b1.y);
    }

#pragma unroll
    for (int i = 0; i < 4; i++) {
        int o = o0 + ty * 4 + i;
        float bias = gen_b[o];
        float r0, r1, r2, r3, r4, r5, r6, r7;
        unpack2(acc[i][0], r0, r1);
        unpack2(acc[i][1], r2, r3);
        unpack2(acc[i][2], r4, r5);
        unpack2(acc[i][3], r6, r7);
        float4 v0 = make_float4(r0 + bias, r1 + bias, r2 + bias, r3 + bias);
        float4 v1 = make_float4(r4 + bias, r5 + bias, r6 + bias, r7 + bias);
        float* dst = g_kern + ((size_t)n * OO + o) * PP + p0 + tx * 8;
        *(float4*)dst = v0;
        *(float4*)(dst + 4) = v1;
    }
}

// ============================================================
// Stage 2: dynamic depthwise convs (d = 1, 3, 5) + build cat buffer
// cat channel blocks: [0:64)=x, [64:128)=r1, [128:192)=r3, [192:256)=r5
// ============================================================
__global__ void __launch_bounds__(256) stage2_dynconv(const float* __restrict__ x)
{
    const int n = blockIdx.z;
    const int c = blockIdx.y;
    const int p = blockIdx.x * 256 + threadIdx.x;
    const int h = p / WW;
    const int w = p - h * WW;

    const float* xc = x + ((size_t)n * CC + c) * PP;
    const float* kb = g_kern + ((size_t)n * OO + c * 9) * PP + p;

    float acc0 = 0.f, acc1 = 0.f, acc2 = 0.f;
#pragma unroll
    for (int tap = 0; tap < 9; tap++) {
        const int di = tap / 3 - 1;
        const int dj = tap % 3 - 1;
        // d = 1
        {
            int hh = h + di, ww2 = w + dj;
            float xv = ((unsigned)hh < (unsigned)HH && (unsigned)ww2 < (unsigned)WW)
                           ? __ldg(xc + hh * WW + ww2) : 0.f;
            acc0 += xv * __ldg(kb + (size_t)tap * PP);
        }
        // d = 3
        {
            int hh = h + di * 3, ww2 = w + dj * 3;
            float xv = ((unsigned)hh < (unsigned)HH && (unsigned)ww2 < (unsigned)WW)
                           ? __ldg(xc + hh * WW + ww2) : 0.f;
            acc1 += xv * __ldg(kb + (size_t)(576 + tap) * PP);
        }
        // d = 5
        {
            int hh = h + di * 5, ww2 = w + dj * 5;
            float xv = ((unsigned)hh < (unsigned)HH && (unsigned)ww2 < (unsigned)WW)
                           ? __ldg(xc + hh * WW + ww2) : 0.f;
            acc2 += xv * __ldg(kb + (size_t)(1152 + tap) * PP);
        }
    }

    float* cb = g_cat + (size_t)n * 4 * CC * PP + p;
    cb[(size_t)c * PP]            = __ldg(xc + p);
    cb[(size_t)(CC + c) * PP]     = acc0;
    cb[(size_t)(2 * CC + c) * PP] = acc1;
    cb[(size_t)(3 * CC + c) * PP] = acc2;
}

// ============================================================
// Small helper: transpose fuse_w [co][ci*9+tap] -> g_wT [k][co]
// ============================================================
__global__ void transpose_w(const float* __restrict__ fuse_w)
{
    int idx = blockIdx.x * 256 + threadIdx.x;  // k*64 + co
    if (idx < KTOT * CC) {
        int k  = idx >> 6;
        int co = idx & 63;
        g_wT[idx] = fuse_w[(size_t)co * KTOT + k];
    }
}

// ============================================================
// Stage 3: out[n,co,p] = fuse_b[co] + sum_{ci,tap} wT[ci*9+tap][co] * cat[n,ci,p+d(tap)]
// Implicit GEMM: tile 64 co x 128 px, K chunked by 32.
// ============================================================
__global__ void __launch_bounds__(256) stage3_conv(
    const float* __restrict__ fuse_b, float* __restrict__ out)
{
    __shared__ __align__(16) float Ws[32][64];    // [kl][co]
    __shared__ __align__(16) float Ps[32][128];   // [kl][px]
    const int n  = blockIdx.z;
    const int p0 = blockIdx.x * 128;
    const int tid = threadIdx.x;
    const int tx = tid & 15, ty = tid >> 4;

    // Per-thread fixed loader coordinates (constant across K chunks)
    const int px  = tid & 127;
    const int klb = tid >> 7;
    const int p = p0 + px;
    const int h = p / WW;
    const int w = p - h * WW;
    const float* catn = g_cat + (size_t)n * 4 * CC * PP;

    unsigned long long acc[4][4];
#pragma unroll
    for (int i = 0; i < 4; i++)
#pragma unroll
        for (int j = 0; j < 4; j++) acc[i][j] = 0ull;

#pragma unroll 1
    for (int kk0 = 0; kk0 < KTOT; kk0 += 32) {
        __syncthreads();
        // Weights: 32x64, coalesced from pre-transposed g_wT
#pragma unroll
        for (int t = 0; t < 8; t++) {
            int kl = (tid >> 6) + t * 4;
            Ws[kl][tid & 63] = __ldg(g_wT + (size_t)(kk0 + kl) * 64 + (tid & 63));
        }
        // Patches: 32x128 gathered from cat with shift + zero-pad
#pragma unroll
        for (int t = 0; t < 16; t++) {
            int kl = klb + t * 2;
            int kk = kk0 + kl;
            int ci  = kk / 9;
            int tap = kk - ci * 9;
            int dy  = tap / 3;
            int dx  = tap - dy * 3;
            int hh  = h + dy - 1;
            int ww2 = w + dx - 1;
            float v = 0.f;
            if ((unsigned)hh < (unsigned)HH && (unsigned)ww2 < (unsigned)WW)
                v = __ldg(catn + (size_t)ci * PP + hh * WW + ww2);
            Ps[kl][px] = v;
        }
        __syncthreads();

#pragma unroll
        for (int kl = 0; kl < 32; kl++) {
            float4 a = *(float4*)&Ws[kl][ty * 4];
            ulonglong2 b0 = *(ulonglong2*)&Ps[kl][tx * 8];
            ulonglong2 b1 = *(ulonglong2*)&Ps[kl][tx * 8 + 4];
            unsigned long long ap0 = pack2(a.x, a.x);
            unsigned long long ap1 = pack2(a.y, a.y);
            unsigned long long ap2 = pack2(a.z, a.z);
            unsigned long long ap3 = pack2(a.w, a.w);
            fma2(acc[0][0], ap0, b0.x); fma2(acc[0][1], ap0, b0.y);
            fma2(acc[0][2], ap0, b1.x); fma2(acc[0][3], ap0, b1.y);
            fma2(acc[1][0], ap1, b0.x); fma2(acc[1][1], ap1, b0.y);
            fma2(acc[1][2], ap1, b1.x); fma2(acc[1][3], ap1, b1.y);
            fma2(acc[2][0], ap2, b0.x); fma2(acc[2][1], ap2, b0.y);
            fma2(acc[2][2], ap2, b1.x); fma2(acc[2][3], ap2, b1.y);
            fma2(acc[3][0], ap3, b0.x); fma2(acc[3][1], ap3, b0.y);
            fma2(acc[3][2], ap3, b1.x); fma2(acc[3][3], ap3, b1.y);
        }
    }

#pragma unroll
    for (int i = 0; i < 4; i++) {
        int co = ty * 4 + i;
        float bias = __ldg(fuse_b + co);
        float r0, r1, r2, r3, r4, r5, r6, r7;
        unpack2(acc[i][0], r0, r1);
        unpack2(acc[i][1], r2, r3);
        unpack2(acc[i][2], r4, r5);
        unpack2(acc[i][3], r6, r7);
        float4 v0 = make_float4(r0 + bias, r1 + bias, r2 + bias, r3 + bias);
        float4 v1 = make_float4(r4 + bias, r5 + bias, r6 + bias, r7 + bias);
        float* dst = out + ((size_t)n * CC + co) * PP + p0 + tx * 8;
        *(float4*)dst = v0;
        *(float4*)(dst + 4) = v1;
    }
}

// ============================================================
extern "C" void kernel_launch(void* const* d_in, const int* in_sizes, int n_in,
                              void* d_out, int out_size)
{
    (void)in_sizes; (void)n_in; (void)out_size;
    const float* x      = (const float*)d_in[0];
    const float* y      = (const float*)d_in[1];
    const float* gen_w  = (const float*)d_in[2];
    const float* gen_b  = (const float*)d_in[3];
    const float* fuse_w = (const float*)d_in[4];
    const float* fuse_b = (const float*)d_in[5];
    float* out = (float*)d_out;

    // Independent prep
    transpose_w<<<(KTOT * CC + 255) / 256, 256>>>(fuse_w);

    // Stage 1: kernel-generation GEMM (per n)
    stage1_gemm<<<dim3(PP / 128, OO / 64, NN), 256>>>(gen_w, gen_b, y);

    // Stage 2: dynamic convs + cat assembly
    stage2_dynconv<<<dim3(PP / 256, CC, NN), 256>>>(x);

    // Stage 3: 3x3 fuse conv
    stage3_conv<<<dim3(PP / 128, 1, NN), 256>>>(fuse_b, out);
}

// round 2
// speedup vs baseline: 1.4341x; 1.4341x over previous
#include <cuda_runtime.h>

// Problem constants
#define NN 4
#define CC 64
#define HH 96
#define WW 96
#define PP (HH * WW)       // 9216 pixels per image
#define OO 1728            // 3 * C * 9 generated kernel channels
#define KTOT 2304          // 256 * 9 reduction dim of fuse conv

// Scratch (alloc-free rule: __device__ globals)
__device__ float g_kern[(size_t)NN * OO * PP];     // per-pixel generated kernels
__device__ float g_cat[(size_t)NN * 4 * CC * PP];  // concat(x, r1, r3, r5)
__device__ float g_wT[KTOT * CC];                  // fuse_w transposed to [k][co]

// ---- packed fp32x2 helpers ----
static __device__ __forceinline__ unsigned long long pack2(float lo, float hi) {
    unsigned long long r;
    asm("mov.b64 %0, {%1,%2};" : "=l"(r) : "f"(lo), "f"(hi));
    return r;
}
static __device__ __forceinline__ void unpack2(unsigned long long v, float& lo, float& hi) {
    asm("mov.b64 {%0,%1}, %2;" : "=f"(lo), "=f"(hi) : "l"(v));
}
static __device__ __forceinline__ void fma2(unsigned long long& d, unsigned long long a, unsigned long long b) {
    asm("fma.rn.f32x2 %0, %1, %2, %3;" : "=l"(d) : "l"(a), "l"(b), "l"(d));
}

// ============================================================
// Stage 1: kern[n,o,p] = sum_k gen_w[o,k] * y[n,k,p] + gen_b[o]
// Tile 64o x 128px, 128 threads, per-thread 16co (8 f32x2 pairs) x 4px.
// A pairs are natural (contiguous co); B pre-duplicated into u64.
// ============================================================
__global__ void __launch_bounds__(128) stage1_gemm(
    const float* __restrict__ gen_w, const float* __restrict__ gen_b,
    const float* __restrict__ y)
{
    __shared__ __align__(16) float As[32][68];                     // [k][o], padded
    __shared__ __align__(16) unsigned long long Bs2[32][128];      // [k][p] dup'd
    const int n  = blockIdx.z;
    const int o0 = blockIdx.y * 64;
    const int p0 = blockIdx.x * 128;
    const int tid = threadIdx.x;
    const int tx = tid & 31;       // px group: 4 px
    const int ty = tid >> 5;       // co group: 16 co

    unsigned long long acc[8][4];
#pragma unroll
    for (int i = 0; i < 8; i++)
#pragma unroll
        for (int j = 0; j < 4; j++) acc[i][j] = 0ull;

    for (int kk0 = 0; kk0 < 64; kk0 += 32) {
        __syncthreads();
        // As: gen_w [64o x 32k] transposed
#pragma unroll
        for (int t = 0; t < 4; t++) {
            int fid = tid + t * 128;          // 0..511
            int o   = fid >> 3;
            int k4  = (fid & 7) * 4;
            float4 v = *(const float4*)(gen_w + (size_t)(o0 + o) * 64 + kk0 + k4);
            As[k4 + 0][o] = v.x;
            As[k4 + 1][o] = v.y;
            As[k4 + 2][o] = v.z;
            As[k4 + 3][o] = v.w;
        }
        // Bs2: y [32k x 128p], duplicated pairs, stored as ulonglong2
#pragma unroll
        for (int t = 0; t < 8; t++) {
            int fid = tid + t * 128;          // 0..1023
            int k   = fid >> 5;
            int p4  = (fid & 31) * 4;
            float4 v = *(const float4*)(y + ((size_t)n * 64 + kk0 + k) * PP + p0 + p4);
            ulonglong2 d0, d1;
            d0.x = pack2(v.x, v.x); d0.y = pack2(v.y, v.y);
            d1.x = pack2(v.z, v.z); d1.y = pack2(v.w, v.w);
            *(ulonglong2*)&Bs2[k][p4]     = d0;
            *(ulonglong2*)&Bs2[k][p4 + 2] = d1;
        }
        __syncthreads();

#pragma unroll 4
        for (int k = 0; k < 32; k++) {
            ulonglong2 a01 = *(ulonglong2*)&As[k][ty * 16];
            ulonglong2 a23 = *(ulonglong2*)&As[k][ty * 16 + 4];
            ulonglong2 a45 = *(ulonglong2*)&As[k][ty * 16 + 8];
            ulonglong2 a67 = *(ulonglong2*)&As[k][ty * 16 + 12];
            ulonglong2 b01 = *(ulonglong2*)&Bs2[k][tx * 4];
            ulonglong2 b23 = *(ulonglong2*)&Bs2[k][tx * 4 + 2];
            fma2(acc[0][0], a01.x, b01.x); fma2(acc[0][1], a01.x, b01.y);
            fma2(acc[0][2], a01.x, b23.x); fma2(acc[0][3], a01.x, b23.y);
            fma2(acc[1][0], a01.y, b01.x); fma2(acc[1][1], a01.y, b01.y);
            fma2(acc[1][2], a01.y, b23.x); fma2(acc[1][3], a01.y, b23.y);
            fma2(acc[2][0], a23.x, b01.x); fma2(acc[2][1], a23.x, b01.y);
            fma2(acc[2][2], a23.x, b23.x); fma2(acc[2][3], a23.x, b23.y);
            fma2(acc[3][0], a23.y, b01.x); fma2(acc[3][1], a23.y, b01.y);
            fma2(acc[3][2], a23.y, b23.x); fma2(acc[3][3], a23.y, b23.y);
            fma2(acc[4][0], a45.x, b01.x); fma2(acc[4][1], a45.x, b01.y);
            fma2(acc[4][2], a45.x, b23.x); fma2(acc[4][3], a45.x, b23.y);
            fma2(acc[5][0], a45.y, b01.x); fma2(acc[5][1], a45.y, b01.y);
            fma2(acc[5][2], a45.y, b23.x); fma2(acc[5][3], a45.y, b23.y);
            fma2(acc[6][0], a67.x, b01.x); fma2(acc[6][1], a67.x, b01.y);
            fma2(acc[6][2], a67.x, b23.x); fma2(acc[6][3], a67.x, b23.y);
            fma2(acc[7][0], a67.y, b01.x); fma2(acc[7][1], a67.y, b01.y);
            fma2(acc[7][2], a67.y, b23.x); fma2(acc[7][3], a67.y, b23.y);
        }
    }

    // Epilogue: acc[i] holds co pair (co0+2i, co0+2i+1) at px tx*4 .. +3
    const int co0 = o0 + ty * 16;
#pragma unroll
    for (int i = 0; i < 8; i++) {
        int oe = co0 + 2 * i;
        float be = gen_b[oe];
        float bo = gen_b[oe + 1];
        float e0, o0v, e1, o1v, e2, o2v, e3, o3v;
        unpack2(acc[i][0], e0, o0v);
        unpack2(acc[i][1], e1, o1v);
        unpack2(acc[i][2], e2, o2v);
        unpack2(acc[i][3], e3, o3v);
        float* de = g_kern + ((size_t)n * OO + oe) * PP + p0 + tx * 4;
        float* doo = de + PP;
        *(float4*)de  = make_float4(e0 + be, e1 + be, e2 + be, e3 + be);
        *(float4*)doo = make_float4(o0v + bo, o1v + bo, o2v + bo, o3v + bo);
    }
}

// ============================================================
// Stage 2: dynamic depthwise convs (d = 1, 3, 5) + build cat buffer
// ============================================================
__global__ void __launch_bounds__(256) stage2_dynconv(const float* __restrict__ x)
{
    const int n = blockIdx.z;
    const int c = blockIdx.y;
    const int p = blockIdx.x * 256 + threadIdx.x;
    const int h = p / WW;
    const int w = p - h * WW;

    const float* xc = x + ((size_t)n * CC + c) * PP;
    const float* kb = g_kern + ((size_t)n * OO + c * 9) * PP + p;

    float acc0 = 0.f, acc1 = 0.f, acc2 = 0.f;
#pragma unroll
    for (int tap = 0; tap < 9; tap++) {
        const int di = tap / 3 - 1;
        const int dj = tap % 3 - 1;
        {
            int hh = h + di, ww2 = w + dj;
            float xv = ((unsigned)hh < (unsigned)HH && (unsigned)ww2 < (unsigned)WW)
                           ? __ldg(xc + hh * WW + ww2) : 0.f;
            acc0 += xv * __ldg(kb + (size_t)tap * PP);
        }
        {
            int hh = h + di * 3, ww2 = w + dj * 3;
            float xv = ((unsigned)hh < (unsigned)HH && (unsigned)ww2 < (unsigned)WW)
                           ? __ldg(xc + hh * WW + ww2) : 0.f;
            acc1 += xv * __ldg(kb + (size_t)(576 + tap) * PP);
        }
        {
            int hh = h + di * 5, ww2 = w + dj * 5;
            float xv = ((unsigned)hh < (unsigned)HH && (unsigned)ww2 < (unsigned)WW)
                           ? __ldg(xc + hh * WW + ww2) : 0.f;
            acc2 += xv * __ldg(kb + (size_t)(1152 + tap) * PP);
        }
    }

    float* cb = g_cat + (size_t)n * 4 * CC * PP + p;
    cb[(size_t)c * PP]            = __ldg(xc + p);
    cb[(size_t)(CC + c) * PP]     = acc0;
    cb[(size_t)(2 * CC + c) * PP] = acc1;
    cb[(size_t)(3 * CC + c) * PP] = acc2;
}

// ============================================================
// transpose fuse_w [co][ci*9+tap] -> g_wT [k][co]
// ============================================================
__global__ void transpose_w(const float* __restrict__ fuse_w)
{
    int idx = blockIdx.x * 256 + threadIdx.x;
    if (idx < KTOT * CC) {
        int k  = idx >> 6;
        int co = idx & 63;
        g_wT[idx] = fuse_w[(size_t)co * KTOT + k];
    }
}

// ============================================================
// Stage 3: 3x3 fuse conv. CTA = one image row (96 px) x 64 co.
// ci processed in groups of 8; 3-row halo in smem (pre-dup'd f32x2).
// Per-thread: 8 co (4 pairs) x 6 px. Threads 128 (tx 16 x ty 8).
// ============================================================
#define S3_G 8
__global__ void __launch_bounds__(128) stage3_conv(
    const float* __restrict__ fuse_b, float* __restrict__ out)
{
    __shared__ __align__(16) float Ws[S3_G * 9][64];                 // [kl][co]
    __shared__ __align__(16) unsigned long long Hal[S3_G][3][100];   // dup'd halo rows
    const int n = blockIdx.y;
    const int h = blockIdx.x;
    const int tid = threadIdx.x;
    const int tx = tid & 15;   // px group: 6 px
    const int ty = tid >> 4;   // co group: 8 co
    const float* catn = g_cat + (size_t)n * 4 * CC * PP;

    unsigned long long acc[4][6];
#pragma unroll
    for (int i = 0; i < 4; i++)
#pragma unroll
        for (int j = 0; j < 6; j++) acc[i][j] = 0ull;

#pragma unroll 1
    for (int c0 = 0; c0 < 4 * CC; c0 += S3_G) {
        __syncthreads();
        // Ws: 72 x 64 from pre-transposed weights
#pragma unroll
        for (int t = 0; t < 9; t++) {
            int fid = tid + t * 128;            // 0..1151
            int kl  = fid >> 4;
            int c4  = (fid & 15) * 4;
            *(float4*)&Ws[kl][c4] = *(const float4*)(g_wT + (size_t)(c0 * 9 + kl) * 64 + c4);
        }
        // Halo: 8 ci x 3 rows x 96 px, duplicated into u64, +1 col offset (w=-1 slot)
#pragma unroll
        for (int t = 0; t < 5; t++) {
            int fid = tid + t * 128;            // need 0..575
            if (fid < 576) {
                int row  = fid / 24;            // 0..23
                int seg  = fid - row * 24;      // 0..23 (4 px each)
                int ci_l = row / 3;
                int dy   = row - ci_l * 3;
                int hh   = h + dy - 1;
                float4 v = make_float4(0.f, 0.f, 0.f, 0.f);
                if ((unsigned)hh < (unsigned)HH)
                    v = *(const float4*)(catn + (size_t)(c0 + ci_l) * PP + hh * WW + seg * 4);
                unsigned long long* dst = &Hal[ci_l][dy][seg * 4 + 1];
                dst[0] = pack2(v.x, v.x);
                dst[1] = pack2(v.y, v.y);
                dst[2] = pack2(v.z, v.z);
                dst[3] = pack2(v.w, v.w);
            }
        }
        // zero the w=-1 and w=96 halo slots
        if (tid < 24) {
            int ci_l = tid / 3, dy = tid % 3;
            Hal[ci_l][dy][0]  = 0ull;
            Hal[ci_l][dy][97] = 0ull;
        }
        __syncthreads();

#pragma unroll 1
        for (int ci_l = 0; ci_l < S3_G; ci_l++) {
#pragma unroll
            for (int dy = 0; dy < 3; dy++) {
                unsigned long long r[8];
#pragma unroll
                for (int t = 0; t < 8; t++) r[t] = Hal[ci_l][dy][tx * 6 + t];
#pragma unroll
                for (int dx = 0; dx < 3; dx++) {
                    int kl = ci_l * 9 + dy * 3 + dx;
                    ulonglong2 aA = *(ulonglong2*)&Ws[kl][ty * 8];
                    ulonglong2 aB = *(ulonglong2*)&Ws[kl][ty * 8 + 4];
#pragma unroll
                    for (int j = 0; j < 6; j++) {
                        unsigned long long b = r[dx + j];
                        fma2(acc[0][j], aA.x, b);
                        fma2(acc[1][j], aA.y, b);
                        fma2(acc[2][j], aB.x, b);
                        fma2(acc[3][j], aB.y, b);
                    }
                }
            }
        }
    }

    // Epilogue: acc[i] = co pair (ty*8+2i, ty*8+2i+1), px = tx*6 + j
    const int px = h * WW + tx * 6;
#pragma unroll
    for (int i = 0; i < 4; i++) {
        int ce = ty * 8 + 2 * i;
        float be = __ldg(fuse_b + ce);
        float bo = __ldg(fuse_b + ce + 1);
        float e[6], o[6];
#pragma unroll
        for (int j = 0; j < 6; j++) unpack2(acc[i][j], e[j], o[j]);
        float* de = out + ((size_t)n * CC + ce) * PP + px;
        float* doo = de + PP;
#pragma unroll
        for (int j = 0; j < 3; j++) {
            *(float2*)(de + 2 * j)  = make_float2(e[2 * j] + be, e[2 * j + 1] + be);
            *(float2*)(doo + 2 * j) = make_float2(o[2 * j] + bo, o[2 * j + 1] + bo);
        }
    }
}

// ============================================================
extern "C" void kernel_launch(void* const* d_in, const int* in_sizes, int n_in,
                              void* d_out, int out_size)
{
    (void)in_sizes; (void)n_in; (void)out_size;
    const float* x      = (const float*)d_in[0];
    const float* y      = (const float*)d_in[1];
    const float* gen_w  = (const float*)d_in[2];
    const float* gen_b  = (const float*)d_in[3];
    const float* fuse_w = (const float*)d_in[4];
    const float* fuse_b = (const float*)d_in[5];
    float* out = (float*)d_out;

    transpose_w<<<(KTOT * CC + 255) / 256, 256>>>(fuse_w);

    stage1_gemm<<<dim3(PP / 128, OO / 64, NN), 128>>>(gen_w, gen_b, y);

    stage2_dynconv<<<dim3(PP / 256, CC, NN), 256>>>(x);

    stage3_conv<<<dim3(HH, NN), 128>>>(fuse_b, out);
}